// round 6
// baseline (speedup 1.0000x reference)
#include <cuda_runtime.h>
#include <math.h>

#define B_BATCH 64
#define D_DIM   768
#define L1_N    8192
#define BRANCH  32
#define TOPK    32
#define NCAND   (TOPK * BRANCH)   // 1024
#define KSPLIT  12
#define KCH     (D_DIM / KSPLIT)  // 64
#define BK      16
#define NT      128               // gemm1 n-tile

// leaf pipeline config
#define LROWS   16                // W1 rows per stage
#define LNSTAGE 4                 // stages per block -> 64 cand/block
#define LBLOCKS 16                // blocks per batch
#define LEAF_SMEM ((D_DIM + 2 * LROWS * D_DIM) * 4)   // xs + double buffer

// ---------------- scratch (allocation-free: static __device__ globals) ----
__device__ float g_part[KSPLIT][B_BATCH * L1_N];   // 24 MB K-split partials
__device__ int   g_sel[B_BATCH * TOPK];
__device__ float g_p0[B_BATCH * TOPK];

// ---------------- packed f32x2 FMA (sm_103a FFMA2) ------------------------
__device__ __forceinline__ unsigned long long ffma2(
    unsigned long long a, unsigned long long b, unsigned long long c)
{
    unsigned long long d;
    asm("fma.rn.f32x2 %0, %1, %2, %3;" : "=l"(d) : "l"(a), "l"(b), "l"(c));
    return d;
}
union F4U { float4 f4; unsigned long long u[2]; float f[4]; };
union UF2 { unsigned long long u; float f[2]; };

__device__ __forceinline__ void cp_async16(void* dst_smem, const void* src)
{
    unsigned d = (unsigned)__cvta_generic_to_shared(dst_smem);
    asm volatile("cp.async.cg.shared.global [%0], [%1], 16;" :: "r"(d), "l"(src));
}

// ---------------- Kernel 1: partial GEMM  logits0 = x @ W0^T --------------
// 64m x 128n block tile, 256 threads, thread tile 4m x 8n (n-paired FFMA2,
// A duplicated in smem). KSPLIT=12 -> grid 768 (~5 CTAs/SM). Smem double
// buffered: one barrier per k-tile.
__global__ __launch_bounds__(256, 4) void gemm1_kernel(
    const float* __restrict__ x, const float* __restrict__ W0,
    const float* __restrict__ b0)
{
    __shared__ float Ad[2][BK][132];   // (a,a) pairs: [buf][k][2m|2m+1]
    __shared__ float Bs[2][BK][132];   // natural    : [buf][k][n]

    const int n0    = blockIdx.x * NT;
    const int ks    = blockIdx.y;
    const int kbase = ks * KCH;
    const int t  = threadIdx.x;
    const int tm = t >> 4;
    const int tn = t & 15;

    const int ar = t >> 2;          // x row   0..63
    const int ac = (t & 3) * 4;     // x k col
    const int br = t >> 1;          // W0 row  0..127
    const int bc = (t & 1) * 8;     // W0 k col base

    unsigned long long acc[4][4] = {};   // [m][n-pair]

    const float* xp = x  + (size_t)ar * D_DIM + kbase + ac;
    const float* bp = W0 + (size_t)(n0 + br) * D_DIM + kbase + bc;

    float4 av  = *(const float4*)xp;
    float4 bv0 = *(const float4*)bp;
    float4 bv1 = *(const float4*)(bp + 4);

    // stage tile 0
    {
        *(float2*)&Ad[0][ac + 0][2 * ar] = make_float2(av.x, av.x);
        *(float2*)&Ad[0][ac + 1][2 * ar] = make_float2(av.y, av.y);
        *(float2*)&Ad[0][ac + 2][2 * ar] = make_float2(av.z, av.z);
        *(float2*)&Ad[0][ac + 3][2 * ar] = make_float2(av.w, av.w);
        Bs[0][bc + 0][br] = bv0.x; Bs[0][bc + 1][br] = bv0.y;
        Bs[0][bc + 2][br] = bv0.z; Bs[0][bc + 3][br] = bv0.w;
        Bs[0][bc + 4][br] = bv1.x; Bs[0][bc + 5][br] = bv1.y;
        Bs[0][bc + 6][br] = bv1.z; Bs[0][bc + 7][br] = bv1.w;
    }
    __syncthreads();

    #pragma unroll
    for (int it = 0; it < KCH / BK; it++) {
        const int buf = it & 1;
        const bool has_next = (it + 1 < KCH / BK);
        if (has_next) {                       // prefetch next tile (overlaps compute)
            av  = *(const float4*)(xp + (it + 1) * BK);
            bv0 = *(const float4*)(bp + (it + 1) * BK);
            bv1 = *(const float4*)(bp + (it + 1) * BK + 4);
        }

        #pragma unroll
        for (int k = 0; k < BK; k++) {
            F4U a01, a23;
            a01.f4 = *(const float4*)&Ad[buf][k][tm * 8];
            a23.f4 = *(const float4*)&Ad[buf][k][tm * 8 + 4];
            unsigned long long bb[4];
            #pragma unroll
            for (int j = 0; j < 4; j++)
                bb[j] = *(const unsigned long long*)&Bs[buf][k][2 * tn + 32 * j];
            #pragma unroll
            for (int j = 0; j < 4; j++) {
                acc[0][j] = ffma2(a01.u[0], bb[j], acc[0][j]);
                acc[1][j] = ffma2(a01.u[1], bb[j], acc[1][j]);
                acc[2][j] = ffma2(a23.u[0], bb[j], acc[2][j]);
                acc[3][j] = ffma2(a23.u[1], bb[j], acc[3][j]);
            }
        }

        if (has_next) {
            const int nb = buf ^ 1;
            *(float2*)&Ad[nb][ac + 0][2 * ar] = make_float2(av.x, av.x);
            *(float2*)&Ad[nb][ac + 1][2 * ar] = make_float2(av.y, av.y);
            *(float2*)&Ad[nb][ac + 2][2 * ar] = make_float2(av.z, av.z);
            *(float2*)&Ad[nb][ac + 3][2 * ar] = make_float2(av.w, av.w);
            Bs[nb][bc + 0][br] = bv0.x; Bs[nb][bc + 1][br] = bv0.y;
            Bs[nb][bc + 2][br] = bv0.z; Bs[nb][bc + 3][br] = bv0.w;
            Bs[nb][bc + 4][br] = bv1.x; Bs[nb][bc + 5][br] = bv1.y;
            Bs[nb][bc + 6][br] = bv1.z; Bs[nb][bc + 7][br] = bv1.w;
        }
        __syncthreads();
    }

    #pragma unroll
    for (int j = 0; j < 4; j++) {
        int n = n0 + 2 * tn + 32 * j;
        float bia0 = (ks == 0) ? b0[n]     : 0.0f;
        float bia1 = (ks == 0) ? b0[n + 1] : 0.0f;
        #pragma unroll
        for (int m = 0; m < 4; m++) {
            UF2 v; v.u = acc[m][j];
            int mg = tm * 4 + m;
            *(float2*)&g_part[ks][(size_t)mg * L1_N + n] =
                make_float2(v.f[0] + bia0, v.f[1] + bia1);
        }
    }
}

// ---------------- Kernel 2: top-32, warp-resident selection loop ----------
__device__ __forceinline__ unsigned long long mkkey(float v, int idx)
{
    unsigned u = __float_as_uint(v);
    u = (u & 0x80000000u) ? ~u : (u | 0x80000000u);
    return ((unsigned long long)u << 32) | (unsigned)(0x7FFFFFFF - idx);
}
__device__ __forceinline__ float keyval(unsigned long long k)
{
    unsigned u = (unsigned)(k >> 32);
    u = (u & 0x80000000u) ? (u & 0x7FFFFFFFu) : ~u;
    return __uint_as_float(u);
}

__global__ __launch_bounds__(256) void topk_kernel()
{
    __shared__ float vals[L1_N];                  // 32 KB
    __shared__ unsigned long long skey[256];
    __shared__ int   pIdx[TOPK];
    __shared__ float pVal[TOPK];

    const int b = blockIdx.x;
    const int t = threadIdx.x;

    for (int i = t; i < L1_N; i += 256) {
        size_t o = (size_t)b * L1_N + i;
        float s = 0.0f;
        #pragma unroll
        for (int p = 0; p < KSPLIT; p++) s += g_part[p][o];
        vals[i] = s;
    }
    __syncthreads();

    {
        unsigned long long kk = 0;
        #pragma unroll
        for (int j = 0; j < L1_N / 256; j++) {
            int idx = t + j * 256;
            unsigned long long c = mkkey(vals[idx], idx);
            if (c > kk) kk = c;
        }
        skey[t] = kk;
    }
    __syncthreads();

    if (t < 32) {
        unsigned long long kr[8];
        #pragma unroll
        for (int r = 0; r < 8; r++) kr[r] = skey[t + 32 * r];

        for (int it = 0; it < TOPK; it++) {
            unsigned long long best = kr[0];
            #pragma unroll
            for (int r = 1; r < 8; r++) if (kr[r] > best) best = kr[r];
            unsigned long long m = best;
            #pragma unroll
            for (int off = 16; off; off >>= 1) {
                unsigned long long o = __shfl_xor_sync(0xffffffffu, m, off);
                if (o > m) m = o;
            }
            int idx = 0x7FFFFFFF - (int)(unsigned)(m & 0xFFFFFFFFull);
            int s   = idx & 255;
            if (t == (s & 31)) {
                vals[idx] = -INFINITY;
                unsigned long long nk = 0;
                #pragma unroll
                for (int j = 0; j < L1_N / 256; j++) {
                    int id2 = s + j * 256;
                    unsigned long long c = mkkey(vals[id2], id2);
                    if (c > nk) nk = c;
                }
                kr[s >> 5] = nk;
            }
            if (t == 0) { pIdx[it] = idx; pVal[it] = keyval(m); }
            __syncwarp();
        }

        if (t == 0) {
            for (int i = 1; i < TOPK; i++) {
                int ki = pIdx[i]; float kv = pVal[i]; int j = i - 1;
                while (j >= 0 && pIdx[j] > ki) {
                    pIdx[j + 1] = pIdx[j]; pVal[j + 1] = pVal[j]; j--;
                }
                pIdx[j + 1] = ki; pVal[j + 1] = kv;
            }
            for (int i = 0; i < TOPK; i++) {
                g_sel[b * TOPK + i] = pIdx[i];
                g_p0[b * TOPK + i]  = 1.0f / (1.0f + expf(-pVal[i]));
            }
        }
    }
}

// ---------------- Kernel 3: leaf scoring, cp.async double-buffer pipeline -
// Block = 64 candidates of one batch, 4 stages x 16 W1 rows (48 KB/stage).
// Stage loads go smem-direct via cp.async (no register staging), so in-flight
// bytes per SM = 2 CTAs x 96 KB >> BW*latency product -> HBM-rate bound.
__global__ __launch_bounds__(256) void leaf_kernel(
    const float* __restrict__ x, const float* __restrict__ W1,
    const float* __restrict__ b1,
    float* __restrict__ probs_out, float* __restrict__ cand_out,
    float* __restrict__ mask_out)
{
    extern __shared__ float sm[];
    float* xs  = sm;                    // [768]
    float* buf = sm + D_DIM;            // [2][LROWS][768]

    const int b   = blockIdx.x >> 4;            // batch
    const int c0  = (blockIdx.x & 15) * (LROWS * LNSTAGE);
    const int t   = threadIdx.x;
    const int w   = t >> 5;
    const int lane = t & 31;

    // stage x[b] into smem
    for (int i = t; i < D_DIM / 4; i += 256)
        ((float4*)xs)[i] = ((const float4*)(x + (size_t)b * D_DIM))[i];

    // issue stage 0 loads
    {
        const int s = 0;
        #pragma unroll
        for (int i = 0; i < (LROWS * D_DIM / 4) / 256; i++) {
            int chunk = t + 256 * i;                 // 16B chunks
            int r   = chunk / (D_DIM / 4);
            int off = chunk % (D_DIM / 4);
            int c   = c0 + s * LROWS + r;
            int leaf = g_sel[b * TOPK + (c >> 5)] * BRANCH + (c & 31);
            cp_async16(buf + ((size_t)(s & 1) * LROWS + r) * D_DIM + off * 4,
                       W1 + (size_t)leaf * D_DIM + off * 4);
        }
        asm volatile("cp.async.commit_group;");
    }

    #pragma unroll
    for (int s = 0; s < LNSTAGE; s++) {
        if (s + 1 < LNSTAGE) {          // issue next stage into other buffer
            #pragma unroll
            for (int i = 0; i < (LROWS * D_DIM / 4) / 256; i++) {
                int chunk = t + 256 * i;
                int r   = chunk / (D_DIM / 4);
                int off = chunk % (D_DIM / 4);
                int c   = c0 + (s + 1) * LROWS + r;
                int leaf = g_sel[b * TOPK + (c >> 5)] * BRANCH + (c & 31);
                cp_async16(buf + ((size_t)((s + 1) & 1) * LROWS + r) * D_DIM + off * 4,
                           W1 + (size_t)leaf * D_DIM + off * 4);
            }
            asm volatile("cp.async.commit_group;");
            asm volatile("cp.async.wait_group 1;");
        } else {
            asm volatile("cp.async.wait_group 0;");
        }
        __syncthreads();

        // compute: warp w handles rows 2w and 2w+1 of this stage
        const float* rowA = buf + ((size_t)(s & 1) * LROWS + 2 * w) * D_DIM;
        const float* rowB = rowA + D_DIM;
        const float4* wrA = (const float4*)rowA;
        const float4* wrB = (const float4*)rowB;
        const float4* xr  = (const float4*)xs;

        unsigned long long a0 = 0, a1 = 0, q0 = 0, q1 = 0;
        #pragma unroll
        for (int q = 0; q < 6; q++) {
            F4U xv; xv.f4 = xr[lane + 32 * q];
            F4U wa; wa.f4 = wrA[lane + 32 * q];
            F4U wb; wb.f4 = wrB[lane + 32 * q];
            a0 = ffma2(wa.u[0], xv.u[0], a0);
            a1 = ffma2(wa.u[1], xv.u[1], a1);
            q0 = ffma2(wb.u[0], xv.u[0], q0);
            q1 = ffma2(wb.u[1], xv.u[1], q1);
        }
        UF2 ua0; ua0.u = a0; UF2 ua1; ua1.u = a1;
        UF2 ub0; ub0.u = q0; UF2 ub1; ub1.u = q1;
        float sA = (ua0.f[0] + ua0.f[1]) + (ua1.f[0] + ua1.f[1]);
        float sB = (ub0.f[0] + ub0.f[1]) + (ub1.f[0] + ub1.f[1]);

        #pragma unroll
        for (int off = 16; off; off >>= 1) {
            sA += __shfl_xor_sync(0xffffffffu, sA, off);
            sB += __shfl_xor_sync(0xffffffffu, sB, off);
        }

        if (lane == 0) {
            const int cA = c0 + s * LROWS + 2 * w;
            const int cB = cA + 1;
            const int iA = cA >> 5, iB = cB >> 5;
            const int leafA = g_sel[b * TOPK + iA] * BRANCH + (cA & 31);
            const int leafB = g_sel[b * TOPK + iB] * BRANCH + (cB & 31);
            float pA = g_p0[b * TOPK + iA] * (1.0f / (1.0f + expf(-(sA + b1[leafA]))));
            float pB = g_p0[b * TOPK + iB] * (1.0f / (1.0f + expf(-(sB + b1[leafB]))));
            int idxA = b * NCAND + cA;
            int idxB = b * NCAND + cB;
            probs_out[idxA] = pA;
            probs_out[idxB] = pB;
            if (cand_out) { cand_out[idxA] = (float)leafA; cand_out[idxB] = (float)leafB; }
            if (mask_out) { mask_out[idxA] = 1.0f;         mask_out[idxB] = 1.0f; }
        }
        __syncthreads();   // buffer (s&1) free for stage s+2's loads
    }
}

// ---------------- launch ----------------
extern "C" void kernel_launch(void* const* d_in, const int* in_sizes, int n_in,
                              void* d_out, int out_size)
{
    const float* x  = (const float*)d_in[0];
    const float* W0 = (const float*)d_in[1];
    const float* b0 = (const float*)d_in[2];
    const float* W1 = (const float*)d_in[3];
    const float* b1 = (const float*)d_in[4];
    float* out = (float*)d_out;

    const int total = B_BATCH * NCAND;  // 65536
    float* probs = out;
    float* cand  = (out_size >= 2 * total) ? out + total     : nullptr;
    float* mask  = (out_size >= 3 * total) ? out + 2 * total : nullptr;

    static int smem_set = 0;   // idempotent attribute set (not a work guard)
    if (!smem_set) {
        cudaFuncSetAttribute(leaf_kernel,
                             cudaFuncAttributeMaxDynamicSharedMemorySize,
                             LEAF_SMEM);
        smem_set = 1;
    }

    gemm1_kernel<<<dim3(L1_N / NT, KSPLIT), 256>>>(x, W0, b0);
    topk_kernel<<<B_BATCH, 256>>>();
    leaf_kernel<<<B_BATCH * LBLOCKS, 256, LEAF_SMEM>>>(x, W1, b1, probs, cand, mask);
}

// round 7
// speedup vs baseline: 1.0425x; 1.0425x over previous
#include <cuda_runtime.h>
#include <math.h>

#define B_BATCH 64
#define D_DIM   768
#define L1_N    8192
#define BRANCH  32
#define TOPK    32
#define NCAND   (TOPK * BRANCH)   // 1024
#define KSPLIT  8
#define KCH     (D_DIM / KSPLIT)  // 96
#define BK      16
#define NT      128               // gemm1 n-tile

// ---------------- scratch (allocation-free: static __device__ globals) ----
__device__ float g_part[KSPLIT][B_BATCH * L1_N];   // 16 MB K-split partials
__device__ int   g_sel[B_BATCH * TOPK];
__device__ float g_p0[B_BATCH * TOPK];

// ---------------- packed f32x2 FMA (sm_103a FFMA2) ------------------------
__device__ __forceinline__ unsigned long long ffma2(
    unsigned long long a, unsigned long long b, unsigned long long c)
{
    unsigned long long d;
    asm("fma.rn.f32x2 %0, %1, %2, %3;" : "=l"(d) : "l"(a), "l"(b), "l"(c));
    return d;
}
union F4U { float4 f4; unsigned long long u[2]; float f[4]; };
union UF2 { unsigned long long u; float f[2]; };

// ---------------- Kernel 1: partial GEMM  logits0 = x @ W0^T --------------
// (R5 configuration verbatim: best measured, 33.3us)
__global__ __launch_bounds__(256) void gemm1_kernel(
    const float* __restrict__ x, const float* __restrict__ W0,
    const float* __restrict__ b0)
{
    __shared__ float Ad[BK][132];   // (a,a) pairs: [k][2m|2m+1]
    __shared__ float Bs[BK][132];   // natural    : [k][n]

    const int n0    = blockIdx.x * NT;
    const int ks    = blockIdx.y;
    const int kbase = ks * KCH;
    const int t  = threadIdx.x;
    const int tm = t >> 4;
    const int tn = t & 15;

    const int ar = t >> 2;
    const int ac = (t & 3) * 4;
    const int br = t >> 1;
    const int bc = (t & 1) * 8;

    unsigned long long acc[4][4] = {};

    const float* xp = x  + (size_t)ar * D_DIM + kbase + ac;
    const float* bp = W0 + (size_t)(n0 + br) * D_DIM + kbase + bc;

    float4 av  = *(const float4*)xp;
    float4 bv0 = *(const float4*)bp;
    float4 bv1 = *(const float4*)(bp + 4);

    for (int k0 = 0; k0 < KCH; k0 += BK) {
        *(float2*)&Ad[ac + 0][2 * ar] = make_float2(av.x, av.x);
        *(float2*)&Ad[ac + 1][2 * ar] = make_float2(av.y, av.y);
        *(float2*)&Ad[ac + 2][2 * ar] = make_float2(av.z, av.z);
        *(float2*)&Ad[ac + 3][2 * ar] = make_float2(av.w, av.w);
        Bs[bc + 0][br] = bv0.x; Bs[bc + 1][br] = bv0.y;
        Bs[bc + 2][br] = bv0.z; Bs[bc + 3][br] = bv0.w;
        Bs[bc + 4][br] = bv1.x; Bs[bc + 5][br] = bv1.y;
        Bs[bc + 6][br] = bv1.z; Bs[bc + 7][br] = bv1.w;
        __syncthreads();

        if (k0 + BK < KCH) {
            av  = *(const float4*)(xp + k0 + BK);
            bv0 = *(const float4*)(bp + k0 + BK);
            bv1 = *(const float4*)(bp + k0 + BK + 4);
        }

        #pragma unroll
        for (int k = 0; k < BK; k++) {
            F4U a01, a23;
            a01.f4 = *(const float4*)&Ad[k][tm * 8];
            a23.f4 = *(const float4*)&Ad[k][tm * 8 + 4];
            unsigned long long bb[4];
            #pragma unroll
            for (int j = 0; j < 4; j++)
                bb[j] = *(const unsigned long long*)&Bs[k][2 * tn + 32 * j];
            #pragma unroll
            for (int j = 0; j < 4; j++) {
                acc[0][j] = ffma2(a01.u[0], bb[j], acc[0][j]);
                acc[1][j] = ffma2(a01.u[1], bb[j], acc[1][j]);
                acc[2][j] = ffma2(a23.u[0], bb[j], acc[2][j]);
                acc[3][j] = ffma2(a23.u[1], bb[j], acc[3][j]);
            }
        }
        __syncthreads();
    }

    #pragma unroll
    for (int j = 0; j < 4; j++) {
        int n = n0 + 2 * tn + 32 * j;
        float bia0 = (ks == 0) ? b0[n]     : 0.0f;
        float bia1 = (ks == 0) ? b0[n + 1] : 0.0f;
        #pragma unroll
        for (int m = 0; m < 4; m++) {
            UF2 v; v.u = acc[m][j];
            int mg = tm * 4 + m;
            *(float2*)&g_part[ks][(size_t)mg * L1_N + n] =
                make_float2(v.f[0] + bia0, v.f[1] + bia1);
        }
    }
}

// ---------------- Kernel 2: top-32, contiguous slices, warp-par rescan ----
__device__ __forceinline__ unsigned long long mkkey(float v, int idx)
{
    unsigned u = __float_as_uint(v);
    u = (u & 0x80000000u) ? ~u : (u | 0x80000000u);
    return ((unsigned long long)u << 32) | (unsigned)(0x7FFFFFFF - idx);
}
__device__ __forceinline__ float keyval(unsigned long long k)
{
    unsigned u = (unsigned)(k >> 32);
    u = (u & 0x80000000u) ? (u & 0x7FFFFFFFu) : ~u;
    return __uint_as_float(u);
}

__global__ __launch_bounds__(256) void topk_kernel()
{
    __shared__ float vals[L1_N];                  // 32 KB
    __shared__ unsigned long long skey[256];
    __shared__ int   pIdx[TOPK];
    __shared__ float pVal[TOPK];

    const int b = blockIdx.x;
    const int t = threadIdx.x;

    // thread t owns contiguous slice [32t, 32t+32). Vectorized partial sum:
    // 8 float4 chunks x KSPLIT partials, KSPLIT-way MLP, L2-resident.
    {
        unsigned long long kk = 0;
        const size_t rb = (size_t)b * L1_N + t * 32;
        #pragma unroll
        for (int c = 0; c < 8; c++) {
            float4 s = make_float4(0.f, 0.f, 0.f, 0.f);
            #pragma unroll
            for (int p = 0; p < KSPLIT; p++) {
                float4 v = *(const float4*)&g_part[p][rb + c * 4];
                s.x += v.x; s.y += v.y; s.z += v.z; s.w += v.w;
            }
            int base = t * 32 + c * 4;
            *(float4*)&vals[base] = s;
            unsigned long long k0 = mkkey(s.x, base);
            unsigned long long k1 = mkkey(s.y, base + 1);
            unsigned long long k2 = mkkey(s.z, base + 2);
            unsigned long long k3 = mkkey(s.w, base + 3);
            if (k1 > k0) k0 = k1;
            if (k3 > k2) k2 = k3;
            if (k2 > k0) k0 = k2;
            if (k0 > kk) kk = k0;
        }
        skey[t] = kk;
    }
    __syncthreads();

    if (t < 32) {
        unsigned long long kr[8];
        #pragma unroll
        for (int r = 0; r < 8; r++) kr[r] = skey[t + 32 * r];

        for (int it = 0; it < TOPK; it++) {
            unsigned long long best = kr[0];
            #pragma unroll
            for (int r = 1; r < 8; r++) if (kr[r] > best) best = kr[r];
            unsigned long long m = best;
            #pragma unroll
            for (int off = 16; off; off >>= 1) {
                unsigned long long o = __shfl_xor_sync(0xffffffffu, m, off);
                if (o > m) m = o;
            }
            int idx = 0x7FFFFFFF - (int)(unsigned)(m & 0xFFFFFFFFull);
            if (t == 0) {
                pIdx[it] = idx; pVal[it] = keyval(m);
                vals[idx] = -INFINITY;
            }
            __syncwarp();
            // warp-parallel rescan of the one changed slice s = idx>>5
            int s = idx >> 5;
            int e = s * 32 + t;                      // lane t reads element t
            unsigned long long nk = mkkey(vals[e], e);
            #pragma unroll
            for (int off = 16; off; off >>= 1) {
                unsigned long long o = __shfl_xor_sync(0xffffffffu, nk, off);
                if (o > nk) nk = o;
            }
            if (t == (s & 31)) kr[s >> 5] = nk;      // owning lane updates reg
        }

        if (t == 0) {
            for (int i = 1; i < TOPK; i++) {   // ascending index sort
                int ki = pIdx[i]; float kv = pVal[i]; int j = i - 1;
                while (j >= 0 && pIdx[j] > ki) {
                    pIdx[j + 1] = pIdx[j]; pVal[j + 1] = pVal[j]; j--;
                }
                pIdx[j + 1] = ki; pVal[j + 1] = kv;
            }
            for (int i = 0; i < TOPK; i++) {
                g_sel[b * TOPK + i] = pIdx[i];
                g_p0[b * TOPK + i]  = 1.0f / (1.0f + expf(-pVal[i]));
            }
        }
    }
}

// ---------------- Kernel 3: gather-score leaves (R5 config verbatim) ------
__global__ __launch_bounds__(256) void leaf_kernel(
    const float* __restrict__ x, const float* __restrict__ W1,
    const float* __restrict__ b1,
    float* __restrict__ probs_out, float* __restrict__ cand_out,
    float* __restrict__ mask_out)
{
    __shared__ float xs[D_DIM];

    const int b  = blockIdx.x >> 6;
    const int c0 = (blockIdx.x & 63) * 16;
    const int t  = threadIdx.x;

    for (int i = t; i < D_DIM / 4; i += 256)
        ((float4*)xs)[i] = ((const float4*)(x + (size_t)b * D_DIM))[i];
    __syncthreads();

    const int w    = t >> 5;
    const int lane = t & 31;
    const int cA   = c0 + w;
    const int cB   = c0 + w + 8;
    const int iA = cA >> 5, jA = cA & 31;
    const int iB = cB >> 5, jB = cB & 31;
    const int leafA = g_sel[b * TOPK + iA] * BRANCH + jA;
    const int leafB = g_sel[b * TOPK + iB] * BRANCH + jB;

    const float4* wrA = (const float4*)(W1 + (size_t)leafA * D_DIM);
    const float4* wrB = (const float4*)(W1 + (size_t)leafB * D_DIM);
    const float4* xr  = (const float4*)xs;

    F4U wa[6], wb[6];
    #pragma unroll
    for (int q = 0; q < 6; q++) wa[q].f4 = __ldcs(wrA + lane + 32 * q);
    #pragma unroll
    for (int q = 0; q < 6; q++) wb[q].f4 = __ldcs(wrB + lane + 32 * q);

    unsigned long long a0 = 0, a1 = 0, b0acc = 0, b1acc = 0;
    #pragma unroll
    for (int q = 0; q < 6; q++) {
        F4U xv; xv.f4 = xr[lane + 32 * q];
        a0    = ffma2(wa[q].u[0], xv.u[0], a0);
        a1    = ffma2(wa[q].u[1], xv.u[1], a1);
        b0acc = ffma2(wb[q].u[0], xv.u[0], b0acc);
        b1acc = ffma2(wb[q].u[1], xv.u[1], b1acc);
    }
    UF2 ua0; ua0.u = a0;    UF2 ua1; ua1.u = a1;
    UF2 ub0; ub0.u = b0acc; UF2 ub1; ub1.u = b1acc;
    float sA = (ua0.f[0] + ua0.f[1]) + (ua1.f[0] + ua1.f[1]);
    float sB = (ub0.f[0] + ub0.f[1]) + (ub1.f[0] + ub1.f[1]);

    #pragma unroll
    for (int off = 16; off; off >>= 1) {
        sA += __shfl_xor_sync(0xffffffffu, sA, off);
        sB += __shfl_xor_sync(0xffffffffu, sB, off);
    }

    if (lane == 0) {
        float lgA = sA + b1[leafA];
        float lgB = sB + b1[leafB];
        float pA = g_p0[b * TOPK + iA] * (1.0f / (1.0f + expf(-lgA)));
        float pB = g_p0[b * TOPK + iB] * (1.0f / (1.0f + expf(-lgB)));
        int idxA = b * NCAND + cA;
        int idxB = b * NCAND + cB;
        probs_out[idxA] = pA;
        probs_out[idxB] = pB;
        if (cand_out) { cand_out[idxA] = (float)leafA; cand_out[idxB] = (float)leafB; }
        if (mask_out) { mask_out[idxA] = 1.0f;         mask_out[idxB] = 1.0f; }
    }
}

// ---------------- launch ----------------
extern "C" void kernel_launch(void* const* d_in, const int* in_sizes, int n_in,
                              void* d_out, int out_size)
{
    const float* x  = (const float*)d_in[0];
    const float* W0 = (const float*)d_in[1];
    const float* b0 = (const float*)d_in[2];
    const float* W1 = (const float*)d_in[3];
    const float* b1 = (const float*)d_in[4];
    float* out = (float*)d_out;

    const int total = B_BATCH * NCAND;  // 65536
    float* probs = out;
    float* cand  = (out_size >= 2 * total) ? out + total     : nullptr;
    float* mask  = (out_size >= 3 * total) ? out + 2 * total : nullptr;

    gemm1_kernel<<<dim3(L1_N / NT, KSPLIT), 256>>>(x, W0, b0);
    topk_kernel<<<B_BATCH, 256>>>();
    leaf_kernel<<<B_BATCH * 64, 256>>>(x, W1, b1, probs, cand, mask);
}

// round 8
// speedup vs baseline: 1.1651x; 1.1176x over previous
#include <cuda_runtime.h>
#include <math.h>

#define B_BATCH 64
#define D_DIM   768
#define L1_N    8192
#define BRANCH  32
#define TOPK    32
#define NCAND   (TOPK * BRANCH)   // 1024
#define PREK    40                // prefilter beam (margin 180 sigma)

// ---------------- scratch ----------------
__device__ float g_logits[B_BATCH * L1_N];   // 2 MB tf32-accurate logits
__device__ int   g_sel[B_BATCH * TOPK];
__device__ float g_p0[B_BATCH * TOPK];

// ---------------- helpers ----------------
__device__ __forceinline__ unsigned long long ffma2(
    unsigned long long a, unsigned long long b, unsigned long long c)
{
    unsigned long long d;
    asm("fma.rn.f32x2 %0, %1, %2, %3;" : "=l"(d) : "l"(a), "l"(b), "l"(c));
    return d;
}
union F4U { float4 f4; unsigned long long u[2]; float f[4]; };
union UF2 { unsigned long long u; float f[2]; };

__device__ __forceinline__ unsigned cvt_tf32(float v)
{
    unsigned r;
    asm("cvt.rna.tf32.f32 %0, %1;" : "=r"(r) : "f"(v));
    return r;
}
__device__ __forceinline__ void st_tf32_4(float* p, float4 v)
{
    uint4 u;
    u.x = cvt_tf32(v.x); u.y = cvt_tf32(v.y);
    u.z = cvt_tf32(v.z); u.w = cvt_tf32(v.w);
    *(uint4*)p = u;
}
__device__ __forceinline__ void mma_tf32(float* c,
    unsigned a0, unsigned a1, unsigned a2, unsigned a3,
    unsigned b0, unsigned b1)
{
    asm("mma.sync.aligned.m16n8k8.row.col.f32.tf32.tf32.f32 "
        "{%0,%1,%2,%3}, {%4,%5,%6,%7}, {%8,%9}, {%0,%1,%2,%3};"
        : "+f"(c[0]), "+f"(c[1]), "+f"(c[2]), "+f"(c[3])
        : "r"(a0), "r"(a1), "r"(a2), "r"(a3), "r"(b0), "r"(b1));
}

// ---------------- Kernel 1: tf32 tensor-core GEMM  logits = x@W0^T + b0 ---
// Block: 64m x 64n, 256 threads = 8 warps (warp = m16 x n32 = 4 n8-tiles).
// K staged in 32-wide chunks ([m][k]/[n][k] smem, stride 36 -> frag loads
// conflict-free: bank = 4g + tc). cvt.rna.tf32 during staging.
__global__ __launch_bounds__(256) void gemm1_tf32_kernel(
    const float* __restrict__ x, const float* __restrict__ W0,
    const float* __restrict__ b0)
{
    __shared__ float As[64][36];   // x     [m][k-chunk]
    __shared__ float Bs[64][36];   // W0    [n][k-chunk]

    const int n0   = blockIdx.x * 64;
    const int t    = threadIdx.x;
    const int lane = t & 31, warp = t >> 5;
    const int g    = lane >> 2, tc = lane & 3;
    const int mt   = (warp & 3) * 16;      // m-tile base row
    const int nh   = (warp >> 2) * 32;     // n-half base col (local)

    // staging: thread owns float4 #t and #(t+256) of the 512-f4 chunk
    const int rs = t >> 3;                  // row 0..31
    const int cs = (t & 7) * 4;             // k-col
    float acc[4][4] = {};                   // [n8-tile][c-frag]

    const float* xp0 = x  + (size_t)rs * D_DIM + cs;
    const float* xp1 = x  + (size_t)(rs + 32) * D_DIM + cs;
    const float* bp0 = W0 + (size_t)(n0 + rs) * D_DIM + cs;
    const float* bp1 = W0 + (size_t)(n0 + rs + 32) * D_DIM + cs;

    float4 pa0 = *(const float4*)xp0;
    float4 pa1 = *(const float4*)xp1;
    float4 pb0 = *(const float4*)bp0;
    float4 pb1 = *(const float4*)bp1;

    #pragma unroll 1
    for (int kc = 0; kc < D_DIM / 32; kc++) {
        st_tf32_4(&As[rs][cs],      pa0);
        st_tf32_4(&As[rs + 32][cs], pa1);
        st_tf32_4(&Bs[rs][cs],      pb0);
        st_tf32_4(&Bs[rs + 32][cs], pb1);
        __syncthreads();

        if (kc + 1 < D_DIM / 32) {          // prefetch next chunk
            pa0 = *(const float4*)(xp0 + (kc + 1) * 32);
            pa1 = *(const float4*)(xp1 + (kc + 1) * 32);
            pb0 = *(const float4*)(bp0 + (kc + 1) * 32);
            pb1 = *(const float4*)(bp1 + (kc + 1) * 32);
        }

        #pragma unroll
        for (int kk = 0; kk < 32; kk += 8) {
            unsigned a0 = __float_as_uint(As[mt + g][kk + tc]);
            unsigned a1 = __float_as_uint(As[mt + g + 8][kk + tc]);
            unsigned a2 = __float_as_uint(As[mt + g][kk + tc + 4]);
            unsigned a3 = __float_as_uint(As[mt + g + 8][kk + tc + 4]);
            #pragma unroll
            for (int nt = 0; nt < 4; nt++) {
                int bn = nh + nt * 8 + g;
                unsigned br0 = __float_as_uint(Bs[bn][kk + tc]);
                unsigned br1 = __float_as_uint(Bs[bn][kk + tc + 4]);
                mma_tf32(acc[nt], a0, a1, a2, a3, br0, br1);
            }
        }
        __syncthreads();
    }

    // epilogue: c0,c1 -> (row mt+g, cols 2tc,2tc+1); c2,c3 -> row +8
    #pragma unroll
    for (int nt = 0; nt < 4; nt++) {
        int col = n0 + nh + nt * 8 + 2 * tc;
        float bi0 = b0[col], bi1 = b0[col + 1];
        int m0 = mt + g;
        *(float2*)&g_logits[(size_t)m0 * L1_N + col] =
            make_float2(acc[nt][0] + bi0, acc[nt][1] + bi1);
        *(float2*)&g_logits[(size_t)(m0 + 8) * L1_N + col] =
            make_float2(acc[nt][2] + bi0, acc[nt][3] + bi1);
    }
}

// ---------------- Kernel 2: prefilter top-40 (tf32) + exact f32 rescore ---
__device__ __forceinline__ unsigned long long mkkey(float v, int idx)
{
    unsigned u = __float_as_uint(v);
    u = (u & 0x80000000u) ? ~u : (u | 0x80000000u);
    return ((unsigned long long)u << 32) | (unsigned)(0x7FFFFFFF - idx);
}
__device__ __forceinline__ float keyval(unsigned long long k)
{
    unsigned u = (unsigned)(k >> 32);
    u = (u & 0x80000000u) ? (u & 0x7FFFFFFFu) : ~u;
    return __uint_as_float(u);
}

__global__ __launch_bounds__(256) void topk_kernel(
    const float* __restrict__ x, const float* __restrict__ W0,
    const float* __restrict__ b0)
{
    __shared__ float vals[L1_N];                  // 32 KB
    __shared__ float xs[D_DIM];
    __shared__ unsigned long long skey[256];
    __shared__ int   idx40[PREK];
    __shared__ float exlog[PREK];
    __shared__ int   pIdx[TOPK];
    __shared__ float pVal[TOPK];

    const int b = blockIdx.x;
    const int t = threadIdx.x;

    // stage x row + logits (coalesced strided), per-thread strided slice keys
    if (t < D_DIM / 4)
        ((float4*)xs)[t] = ((const float4*)(x + (size_t)b * D_DIM))[t];
    {
        unsigned long long kk = 0;
        #pragma unroll
        for (int j = 0; j < L1_N / 256; j++) {
            int i = t + j * 256;
            float v = g_logits[(size_t)b * L1_N + i];
            vals[i] = v;
            unsigned long long c = mkkey(v, i);
            if (c > kk) kk = c;
        }
        skey[t] = kk;
    }
    __syncthreads();

    // warp 0: incremental top-40 (R5-proven structure)
    if (t < 32) {
        unsigned long long kr[8];
        #pragma unroll
        for (int r = 0; r < 8; r++) kr[r] = skey[t + 32 * r];

        for (int it = 0; it < PREK; it++) {
            unsigned long long best = kr[0];
            #pragma unroll
            for (int r = 1; r < 8; r++) if (kr[r] > best) best = kr[r];
            unsigned long long m = best;
            #pragma unroll
            for (int off = 16; off; off >>= 1) {
                unsigned long long o = __shfl_xor_sync(0xffffffffu, m, off);
                if (o > m) m = o;
            }
            int idx = 0x7FFFFFFF - (int)(unsigned)(m & 0xFFFFFFFFull);
            int s   = idx & 255;
            if (t == (s & 31)) {               // owner refreshes its slice
                vals[idx] = -INFINITY;
                unsigned long long nk = 0;
                #pragma unroll
                for (int j = 0; j < L1_N / 256; j++) {
                    int i2 = s + j * 256;
                    unsigned long long c = mkkey(vals[i2], i2);
                    if (c > nk) nk = c;
                }
                kr[s >> 5] = nk;
            }
            if (t == 0) idx40[it] = idx;
            __syncwarp();
        }
    }
    __syncthreads();

    // all 8 warps: exact f32 rescore of the 40 candidate groups
    {
        const int w = t >> 5, lane = t & 31;
        for (int c = w; c < PREK; c += 8) {
            int gi = idx40[c];
            const float4* wr = (const float4*)(W0 + (size_t)gi * D_DIM);
            const float4* xr = (const float4*)xs;
            float acc = 0.0f;
            #pragma unroll
            for (int q = 0; q < 6; q++) {
                float4 wv = wr[lane + 32 * q];
                float4 xv = xr[lane + 32 * q];
                acc = fmaf(wv.x, xv.x, acc);
                acc = fmaf(wv.y, xv.y, acc);
                acc = fmaf(wv.z, xv.z, acc);
                acc = fmaf(wv.w, xv.w, acc);
            }
            #pragma unroll
            for (int off = 16; off; off >>= 1)
                acc += __shfl_xor_sync(0xffffffffu, acc, off);
            if (lane == 0) exlog[c] = acc + b0[gi];
        }
    }
    __syncthreads();

    // warp 0: exact top-32 of the 40 rescored (tie -> lowest group index)
    if (t < 32) {
        unsigned long long r0 = mkkey(exlog[t], idx40[t]);
        unsigned long long r1 = (t < PREK - 32)
            ? mkkey(exlog[32 + t], idx40[32 + t]) : 0ull;

        for (int it = 0; it < TOPK; it++) {
            unsigned long long m = (r0 > r1) ? r0 : r1;
            #pragma unroll
            for (int off = 16; off; off >>= 1) {
                unsigned long long o = __shfl_xor_sync(0xffffffffu, m, off);
                if (o > m) m = o;
            }
            if (r0 == m) r0 = 0ull;           // unique keys: only owner clears
            if (r1 == m) r1 = 0ull;
            if (t == 0) {
                pIdx[it] = 0x7FFFFFFF - (int)(unsigned)(m & 0xFFFFFFFFull);
                pVal[it] = keyval(m);
            }
            __syncwarp();
        }

        if (t == 0) {
            for (int i = 1; i < TOPK; i++) {  // ascending group-index sort
                int ki = pIdx[i]; float kv = pVal[i]; int j = i - 1;
                while (j >= 0 && pIdx[j] > ki) {
                    pIdx[j + 1] = pIdx[j]; pVal[j + 1] = pVal[j]; j--;
                }
                pIdx[j + 1] = ki; pVal[j + 1] = kv;
            }
            for (int i = 0; i < TOPK; i++) {
                g_sel[b * TOPK + i] = pIdx[i];
                g_p0[b * TOPK + i]  = 1.0f / (1.0f + expf(-pVal[i]));
            }
        }
    }
}

// ---------------- Kernel 3: gather-score leaves (R5 config verbatim) ------
__global__ __launch_bounds__(256) void leaf_kernel(
    const float* __restrict__ x, const float* __restrict__ W1,
    const float* __restrict__ b1,
    float* __restrict__ probs_out, float* __restrict__ cand_out,
    float* __restrict__ mask_out)
{
    __shared__ float xs[D_DIM];

    const int b  = blockIdx.x >> 6;
    const int c0 = (blockIdx.x & 63) * 16;
    const int t  = threadIdx.x;

    for (int i = t; i < D_DIM / 4; i += 256)
        ((float4*)xs)[i] = ((const float4*)(x + (size_t)b * D_DIM))[i];
    __syncthreads();

    const int w    = t >> 5;
    const int lane = t & 31;
    const int cA   = c0 + w;
    const int cB   = c0 + w + 8;
    const int iA = cA >> 5, jA = cA & 31;
    const int iB = cB >> 5, jB = cB & 31;
    const int leafA = g_sel[b * TOPK + iA] * BRANCH + jA;
    const int leafB = g_sel[b * TOPK + iB] * BRANCH + jB;

    const float4* wrA = (const float4*)(W1 + (size_t)leafA * D_DIM);
    const float4* wrB = (const float4*)(W1 + (size_t)leafB * D_DIM);
    const float4* xr  = (const float4*)xs;

    F4U wa[6], wb[6];
    #pragma unroll
    for (int q = 0; q < 6; q++) wa[q].f4 = __ldcs(wrA + lane + 32 * q);
    #pragma unroll
    for (int q = 0; q < 6; q++) wb[q].f4 = __ldcs(wrB + lane + 32 * q);

    unsigned long long a0 = 0, a1 = 0, b0acc = 0, b1acc = 0;
    #pragma unroll
    for (int q = 0; q < 6; q++) {
        F4U xv; xv.f4 = xr[lane + 32 * q];
        a0    = ffma2(wa[q].u[0], xv.u[0], a0);
        a1    = ffma2(wa[q].u[1], xv.u[1], a1);
        b0acc = ffma2(wb[q].u[0], xv.u[0], b0acc);
        b1acc = ffma2(wb[q].u[1], xv.u[1], b1acc);
    }
    UF2 ua0; ua0.u = a0;    UF2 ua1; ua1.u = a1;
    UF2 ub0; ub0.u = b0acc; UF2 ub1; ub1.u = b1acc;
    float sA = (ua0.f[0] + ua0.f[1]) + (ua1.f[0] + ua1.f[1]);
    float sB = (ub0.f[0] + ub0.f[1]) + (ub1.f[0] + ub1.f[1]);

    #pragma unroll
    for (int off = 16; off; off >>= 1) {
        sA += __shfl_xor_sync(0xffffffffu, sA, off);
        sB += __shfl_xor_sync(0xffffffffu, sB, off);
    }

    if (lane == 0) {
        float lgA = sA + b1[leafA];
        float lgB = sB + b1[leafB];
        float pA = g_p0[b * TOPK + iA] * (1.0f / (1.0f + expf(-lgA)));
        float pB = g_p0[b * TOPK + iB] * (1.0f / (1.0f + expf(-lgB)));
        int idxA = b * NCAND + cA;
        int idxB = b * NCAND + cB;
        probs_out[idxA] = pA;
        probs_out[idxB] = pB;
        if (cand_out) { cand_out[idxA] = (float)leafA; cand_out[idxB] = (float)leafB; }
        if (mask_out) { mask_out[idxA] = 1.0f;         mask_out[idxB] = 1.0f; }
    }
}

// ---------------- launch ----------------
extern "C" void kernel_launch(void* const* d_in, const int* in_sizes, int n_in,
                              void* d_out, int out_size)
{
    const float* x  = (const float*)d_in[0];
    const float* W0 = (const float*)d_in[1];
    const float* b0 = (const float*)d_in[2];
    const float* W1 = (const float*)d_in[3];
    const float* b1 = (const float*)d_in[4];
    float* out = (float*)d_out;

    const int total = B_BATCH * NCAND;  // 65536
    float* probs = out;
    float* cand  = (out_size >= 2 * total) ? out + total     : nullptr;
    float* mask  = (out_size >= 3 * total) ? out + 2 * total : nullptr;

    gemm1_tf32_kernel<<<L1_N / 64, 256>>>(x, W0, b0);
    topk_kernel<<<B_BATCH, 256>>>(x, W0, b0);
    leaf_kernel<<<B_BATCH * 64, 256>>>(x, W1, b1, probs, cand, mask);
}

// round 9
// speedup vs baseline: 1.1684x; 1.0029x over previous
#include <cuda_runtime.h>
#include <math.h>

#define B_BATCH 64
#define D_DIM   768
#define L1_N    8192
#define BRANCH  32
#define TOPK    32
#define NCAND   (TOPK * BRANCH)   // 1024
#define PREK    40                // prefilter beam (margin ~180 sigma)
#define NSTG    3                 // gemm cp.async stages
#define KSTEPS  (D_DIM / 32)      // 24

// ---------------- scratch ----------------
__device__ float g_logits[B_BATCH * L1_N];   // 2 MB tf32-accurate logits
__device__ int   g_sel[B_BATCH * TOPK];
__device__ float g_p0[B_BATCH * TOPK];

// ---------------- helpers ----------------
__device__ __forceinline__ unsigned long long ffma2(
    unsigned long long a, unsigned long long b, unsigned long long c)
{
    unsigned long long d;
    asm("fma.rn.f32x2 %0, %1, %2, %3;" : "=l"(d) : "l"(a), "l"(b), "l"(c));
    return d;
}
union F4U { float4 f4; unsigned long long u[2]; float f[4]; };
union UF2 { unsigned long long u; float f[2]; };

__device__ __forceinline__ void cp_async16(void* dst_smem, const void* src)
{
    unsigned d = (unsigned)__cvta_generic_to_shared(dst_smem);
    asm volatile("cp.async.cg.shared.global [%0], [%1], 16;" :: "r"(d), "l"(src));
}
__device__ __forceinline__ void mma_tf32(float* c,
    unsigned a0, unsigned a1, unsigned a2, unsigned a3,
    unsigned b0, unsigned b1)
{
    asm("mma.sync.aligned.m16n8k8.row.col.f32.tf32.tf32.f32 "
        "{%0,%1,%2,%3}, {%4,%5,%6,%7}, {%8,%9}, {%0,%1,%2,%3};"
        : "+f"(c[0]), "+f"(c[1]), "+f"(c[2]), "+f"(c[3])
        : "r"(a0), "r"(a1), "r"(a2), "r"(a3), "r"(b0), "r"(b1));
}

// ---------------- Kernel 1: tf32 GEMM, 3-stage cp.async pipeline ----------
// Block 64m x 32n, 256 threads = 8 warps; warp = m16 x n16 (2 n8-tiles).
// Stage = k32 chunk: A 64x32 + B 32x32 smem-direct via LDGSTS (no regs held)
// -> deep in-flight byte count, DRAM-rate streaming of W0.
// f32 bits fed to mma.tf32 untruncated (HW ignores low mantissa bits);
// selection is later rescored in exact f32, so prefilter precision suffices.
__global__ __launch_bounds__(256) void gemm1_tf32_kernel(
    const float* __restrict__ x, const float* __restrict__ W0,
    const float* __restrict__ b0)
{
    __shared__ float As[NSTG][64][36];
    __shared__ float Bs[NSTG][32][36];

    const int n0   = blockIdx.x * 32;
    const int t    = threadIdx.x;
    const int lane = t & 31, warp = t >> 5;
    const int g    = lane >> 2, tc = lane & 3;
    const int mt   = (warp & 3) * 16;       // m-tile base
    const int nh   = (warp >> 2) * 16;      // n-half base (local)

    // staging coords: A chunks t and t+256 (of 512), B chunk t (of 256)
    const int ars0 = t >> 3;                 // A row for chunk t       (0..31)
    const int ars1 = (t + 256) >> 3;         // A row for chunk t+256   (32..63)
    const int acs  = (t & 7) * 4;            // k col
    const int brs  = t >> 3;                 // B row (0..31)

    const float* xp0 = x  + (size_t)ars0 * D_DIM + acs;
    const float* xp1 = x  + (size_t)ars1 * D_DIM + acs;
    const float* bp  = W0 + (size_t)(n0 + brs) * D_DIM + acs;

    float acc[2][4] = {};                    // [n8-tile][c-frag]

    // prologue: issue stages 0..NSTG-2
    #pragma unroll
    for (int s = 0; s < NSTG - 1; s++) {
        cp_async16(&As[s][ars0][acs], xp0 + s * 32);
        cp_async16(&As[s][ars1][acs], xp1 + s * 32);
        cp_async16(&Bs[s][brs][acs],  bp  + s * 32);
        asm volatile("cp.async.commit_group;");
    }

    #pragma unroll 1
    for (int kc = 0; kc < KSTEPS; kc++) {
        const int buf = kc % NSTG;
        asm volatile("cp.async.wait_group %0;" :: "n"(NSTG - 2));
        __syncthreads();

        if (kc + NSTG - 1 < KSTEPS) {        // issue stage kc+NSTG-1
            const int s  = kc + NSTG - 1;
            const int nb = s % NSTG;
            cp_async16(&As[nb][ars0][acs], xp0 + s * 32);
            cp_async16(&As[nb][ars1][acs], xp1 + s * 32);
            cp_async16(&Bs[nb][brs][acs],  bp  + s * 32);
            asm volatile("cp.async.commit_group;");
        } else {
            asm volatile("cp.async.commit_group;");   // keep group count in step
        }

        #pragma unroll
        for (int kk = 0; kk < 32; kk += 8) {
            unsigned a0 = __float_as_uint(As[buf][mt + g][kk + tc]);
            unsigned a1 = __float_as_uint(As[buf][mt + g + 8][kk + tc]);
            unsigned a2 = __float_as_uint(As[buf][mt + g][kk + tc + 4]);
            unsigned a3 = __float_as_uint(As[buf][mt + g + 8][kk + tc + 4]);
            #pragma unroll
            for (int nt = 0; nt < 2; nt++) {
                int bn = nh + nt * 8 + g;
                unsigned br0 = __float_as_uint(Bs[buf][bn][kk + tc]);
                unsigned br1 = __float_as_uint(Bs[buf][bn][kk + tc + 4]);
                mma_tf32(acc[nt], a0, a1, a2, a3, br0, br1);
            }
        }
        __syncthreads();
    }

    #pragma unroll
    for (int nt = 0; nt < 2; nt++) {
        int col = n0 + nh + nt * 8 + 2 * tc;
        float bi0 = b0[col], bi1 = b0[col + 1];
        int m0 = mt + g;
        *(float2*)&g_logits[(size_t)m0 * L1_N + col] =
            make_float2(acc[nt][0] + bi0, acc[nt][1] + bi1);
        *(float2*)&g_logits[(size_t)(m0 + 8) * L1_N + col] =
            make_float2(acc[nt][2] + bi0, acc[nt][3] + bi1);
    }
}

// ---------------- Kernel 2: prefilter top-40 + exact f32 rescore ----------
__device__ __forceinline__ unsigned long long mkkey(float v, int idx)
{
    unsigned u = __float_as_uint(v);
    u = (u & 0x80000000u) ? ~u : (u | 0x80000000u);
    return ((unsigned long long)u << 32) | (unsigned)(0x7FFFFFFF - idx);
}
__device__ __forceinline__ float keyval(unsigned long long k)
{
    unsigned u = (unsigned)(k >> 32);
    u = (u & 0x80000000u) ? (u & 0x7FFFFFFFu) : ~u;
    return __uint_as_float(u);
}

__global__ __launch_bounds__(256) void topk_kernel(
    const float* __restrict__ x, const float* __restrict__ W0,
    const float* __restrict__ b0)
{
    __shared__ float vals[L1_N];                  // 32 KB
    __shared__ float xs[D_DIM];
    __shared__ unsigned long long skey[256];
    __shared__ int   idx40[PREK];
    __shared__ float exlog[PREK];
    __shared__ int   pIdx[TOPK];
    __shared__ float pVal[TOPK];

    const int b = blockIdx.x;
    const int t = threadIdx.x;

    if (t < D_DIM / 4)
        ((float4*)xs)[t] = ((const float4*)(x + (size_t)b * D_DIM))[t];
    {
        unsigned long long kk = 0;
        #pragma unroll
        for (int j = 0; j < L1_N / 256; j++) {
            int i = t + j * 256;
            float v = g_logits[(size_t)b * L1_N + i];
            vals[i] = v;
            unsigned long long c = mkkey(v, i);
            if (c > kk) kk = c;
        }
        skey[t] = kk;
    }
    __syncthreads();

    if (t < 32) {
        unsigned long long kr[8];
        #pragma unroll
        for (int r = 0; r < 8; r++) kr[r] = skey[t + 32 * r];

        for (int it = 0; it < PREK; it++) {
            unsigned long long best = kr[0];
            #pragma unroll
            for (int r = 1; r < 8; r++) if (kr[r] > best) best = kr[r];
            unsigned long long m = best;
            #pragma unroll
            for (int off = 16; off; off >>= 1) {
                unsigned long long o = __shfl_xor_sync(0xffffffffu, m, off);
                if (o > m) m = o;
            }
            int idx = 0x7FFFFFFF - (int)(unsigned)(m & 0xFFFFFFFFull);
            int s   = idx & 255;
            if (t == (s & 31)) {
                vals[idx] = -INFINITY;
                unsigned long long nk = 0;
                #pragma unroll
                for (int j = 0; j < L1_N / 256; j++) {
                    int i2 = s + j * 256;
                    unsigned long long c = mkkey(vals[i2], i2);
                    if (c > nk) nk = c;
                }
                kr[s >> 5] = nk;
            }
            if (t == 0) idx40[it] = idx;
            __syncwarp();
        }
    }
    __syncthreads();

    // exact f32 rescore of the 40 candidate groups (all warps)
    {
        const int w = t >> 5, lane = t & 31;
        for (int c = w; c < PREK; c += 8) {
            int gi = idx40[c];
            const float4* wr = (const float4*)(W0 + (size_t)gi * D_DIM);
            const float4* xr = (const float4*)xs;
            float acc = 0.0f;
            #pragma unroll
            for (int q = 0; q < 6; q++) {
                float4 wv = wr[lane + 32 * q];
                float4 xv = xr[lane + 32 * q];
                acc = fmaf(wv.x, xv.x, acc);
                acc = fmaf(wv.y, xv.y, acc);
                acc = fmaf(wv.z, xv.z, acc);
                acc = fmaf(wv.w, xv.w, acc);
            }
            #pragma unroll
            for (int off = 16; off; off >>= 1)
                acc += __shfl_xor_sync(0xffffffffu, acc, off);
            if (lane == 0) exlog[c] = acc + b0[gi];
        }
    }
    __syncthreads();

    if (t < 32) {
        unsigned long long r0 = mkkey(exlog[t], idx40[t]);
        unsigned long long r1 = (t < PREK - 32)
            ? mkkey(exlog[32 + t], idx40[32 + t]) : 0ull;

        for (int it = 0; it < TOPK; it++) {
            unsigned long long m = (r0 > r1) ? r0 : r1;
            #pragma unroll
            for (int off = 16; off; off >>= 1) {
                unsigned long long o = __shfl_xor_sync(0xffffffffu, m, off);
                if (o > m) m = o;
            }
            if (r0 == m) r0 = 0ull;
            if (r1 == m) r1 = 0ull;
            if (t == 0) {
                pIdx[it] = 0x7FFFFFFF - (int)(unsigned)(m & 0xFFFFFFFFull);
                pVal[it] = keyval(m);
            }
            __syncwarp();
        }

        if (t == 0) {
            for (int i = 1; i < TOPK; i++) {
                int ki = pIdx[i]; float kv = pVal[i]; int j = i - 1;
                while (j >= 0 && pIdx[j] > ki) {
                    pIdx[j + 1] = pIdx[j]; pVal[j + 1] = pVal[j]; j--;
                }
                pIdx[j + 1] = ki; pVal[j + 1] = kv;
            }
            for (int i = 0; i < TOPK; i++) {
                g_sel[b * TOPK + i] = pIdx[i];
                g_p0[b * TOPK + i]  = 1.0f / (1.0f + expf(-pVal[i]));
            }
        }
    }
}

// ---------------- Kernel 3: gather-score leaves (R5 config verbatim) ------
__global__ __launch_bounds__(256) void leaf_kernel(
    const float* __restrict__ x, const float* __restrict__ W1,
    const float* __restrict__ b1,
    float* __restrict__ probs_out, float* __restrict__ cand_out,
    float* __restrict__ mask_out)
{
    __shared__ float xs[D_DIM];

    const int b  = blockIdx.x >> 6;
    const int c0 = (blockIdx.x & 63) * 16;
    const int t  = threadIdx.x;

    for (int i = t; i < D_DIM / 4; i += 256)
        ((float4*)xs)[i] = ((const float4*)(x + (size_t)b * D_DIM))[i];
    __syncthreads();

    const int w    = t >> 5;
    const int lane = t & 31;
    const int cA   = c0 + w;
    const int cB   = c0 + w + 8;
    const int iA = cA >> 5, jA = cA & 31;
    const int iB = cB >> 5, jB = cB & 31;
    const int leafA = g_sel[b * TOPK + iA] * BRANCH + jA;
    const int leafB = g_sel[b * TOPK + iB] * BRANCH + jB;

    const float4* wrA = (const float4*)(W1 + (size_t)leafA * D_DIM);
    const float4* wrB = (const float4*)(W1 + (size_t)leafB * D_DIM);
    const float4* xr  = (const float4*)xs;

    F4U wa[6], wb[6];
    #pragma unroll
    for (int q = 0; q < 6; q++) wa[q].f4 = __ldcs(wrA + lane + 32 * q);
    #pragma unroll
    for (int q = 0; q < 6; q++) wb[q].f4 = __ldcs(wrB + lane + 32 * q);

    unsigned long long a0 = 0, a1 = 0, b0acc = 0, b1acc = 0;
    #pragma unroll
    for (int q = 0; q < 6; q++) {
        F4U xv; xv.f4 = xr[lane + 32 * q];
        a0    = ffma2(wa[q].u[0], xv.u[0], a0);
        a1    = ffma2(wa[q].u[1], xv.u[1], a1);
        b0acc = ffma2(wb[q].u[0], xv.u[0], b0acc);
        b1acc = ffma2(wb[q].u[1], xv.u[1], b1acc);
    }
    UF2 ua0; ua0.u = a0;    UF2 ua1; ua1.u = a1;
    UF2 ub0; ub0.u = b0acc; UF2 ub1; ub1.u = b1acc;
    float sA = (ua0.f[0] + ua0.f[1]) + (ua1.f[0] + ua1.f[1]);
    float sB = (ub0.f[0] + ub0.f[1]) + (ub1.f[0] + ub1.f[1]);

    #pragma unroll
    for (int off = 16; off; off >>= 1) {
        sA += __shfl_xor_sync(0xffffffffu, sA, off);
        sB += __shfl_xor_sync(0xffffffffu, sB, off);
    }

    if (lane == 0) {
        float lgA = sA + b1[leafA];
        float lgB = sB + b1[leafB];
        float pA = g_p0[b * TOPK + iA] * (1.0f / (1.0f + expf(-lgA)));
        float pB = g_p0[b * TOPK + iB] * (1.0f / (1.0f + expf(-lgB)));
        int idxA = b * NCAND + cA;
        int idxB = b * NCAND + cB;
        probs_out[idxA] = pA;
        probs_out[idxB] = pB;
        if (cand_out) { cand_out[idxA] = (float)leafA; cand_out[idxB] = (float)leafB; }
        if (mask_out) { mask_out[idxA] = 1.0f;         mask_out[idxB] = 1.0f; }
    }
}

// ---------------- launch ----------------
extern "C" void kernel_launch(void* const* d_in, const int* in_sizes, int n_in,
                              void* d_out, int out_size)
{
    const float* x  = (const float*)d_in[0];
    const float* W0 = (const float*)d_in[1];
    const float* b0 = (const float*)d_in[2];
    const float* W1 = (const float*)d_in[3];
    const float* b1 = (const float*)d_in[4];
    float* out = (float*)d_out;

    const int total = B_BATCH * NCAND;  // 65536
    float* probs = out;
    float* cand  = (out_size >= 2 * total) ? out + total     : nullptr;
    float* mask  = (out_size >= 3 * total) ? out + 2 * total : nullptr;

    gemm1_tf32_kernel<<<L1_N / 32, 256>>>(x, W0, b0);
    topk_kernel<<<B_BATCH, 256>>>(x, W0, b0);
    leaf_kernel<<<B_BATCH * 64, 256>>>(x, W1, b1, probs, cand, mask);
}